// round 8
// baseline (speedup 1.0000x reference)
#include <cuda_runtime.h>
#include <math.h>

#define BATCH   16
#define HEADS   16
#define DIM     128
#define BS      16
#define MAX_CTX 1024
#define NTBL    96
#define PT_LEN  32
#define QSCALE  0.08838834764831845f
#define CHUNK   32
#define NCHUNK  32
#define NEG_INF -1e30f

__device__ float        g_m  [BATCH*HEADS*NCHUNK];
__device__ float        g_l  [BATCH*HEADS*NCHUNK];
__device__ float        g_acc[BATCH*HEADS*NCHUNK*DIM];
__device__ unsigned int g_cnt[BATCH*HEADS];          // zero-init; merger resets

__global__ void __launch_bounds__(128, 6) attn_fused(
    const float* __restrict__ q,
    const float* __restrict__ k_new,
    const float* __restrict__ v_new,
    const float* __restrict__ kc,
    const float* __restrict__ vc,
    const int*   __restrict__ btab,
    const int*   __restrict__ ctx_lens,
    const float* __restrict__ bias,
    float*       __restrict__ out)
{
    const int chunk = blockIdx.x;
    const int h     = blockIdx.y;
    const int b     = blockIdx.z;
    const int ctx   = ctx_lens[b];
    const int start = chunk * CHUNK;
    if (start >= ctx) return;

    const int t    = threadIdx.x;          // 0..127
    const int wid  = t >> 5;
    const int lane = t & 31;
    const int bh   = b*HEADS + h;
    const int npos = min(CHUNK, ctx - start);
    const int last = ctx - 1;

    __shared__ float shK[CHUNK*DIM];       // 16 KB, row-major per position
    __shared__ float shV[2*4*DIM*4];       // 16 KB, [block][j4][dim] 16B slots (transposed)
    __shared__ float sh_s[CHUNK];
    __shared__ float sh_b[CHUNK];
    __shared__ int   sh_blk[CHUNK/BS];
    __shared__ float sh_red[3];

    if (t < CHUNK/BS) sh_blk[t] = btab[b*NTBL + PT_LEN + chunk*(CHUNK/BS) + t];
    if (t < CHUNK)    sh_b[t]   = bias[(size_t)bh*MAX_CTX + start + t];

    float4 q4 = ((const float4*)(q + (size_t)bh*DIM))[lane];
    q4.x *= QSCALE; q4.y *= QSCALE; q4.z *= QSCALE; q4.w *= QSCALE;
    const float vn = v_new[(size_t)bh*DIM + t];
    __syncthreads();

    // ---------- Group 1: K rows (warp wid owns rows wid*8..wid*8+7) ----------
    {
        const int kb   = wid >> 1;
        const int rb   = (wid & 1) * 8;
        const float* kbase = kc + ((size_t)sh_blk[kb]*HEADS + h)*(BS*DIM) + rb*DIM;
        const float* knewp = k_new + (size_t)bh*DIM;
        const unsigned dbase = (unsigned)__cvta_generic_to_shared(&shK[wid*8*DIM]) + lane*16u;
        #pragma unroll
        for (int r = 0; r < 8; ++r) {
            const int pos = start + wid*8 + r;
            const float* src = ((pos == last) ? knewp : (kbase + r*DIM)) + lane*4;
            asm volatile("cp.async.cg.shared.global [%0], [%1], 16;\n"
                         :: "r"(dbase + r*(DIM*4u)), "l"(src) : "memory");
        }
        asm volatile("cp.async.commit_group;\n" ::: "memory");
    }

    // ---------- Group 2: V, transposed scatter: slot(kb,j4,d=t) <- vc[d=t][4*j4..] ----------
    {
        const unsigned vsh = (unsigned)__cvta_generic_to_shared(shV);
        #pragma unroll
        for (int kb = 0; kb < 2; ++kb) {
            const float* vsrc = vc + (((size_t)sh_blk[kb]*HEADS + h)*DIM + t)*BS;
            #pragma unroll
            for (int j4 = 0; j4 < 4; ++j4) {
                asm volatile("cp.async.cg.shared.global [%0], [%1], 16;\n"
                             :: "r"(vsh + (kb*512u + j4*128u + t)*16u),
                                "l"(vsrc + j4*4) : "memory");
            }
        }
        asm volatile("cp.async.commit_group;\n" ::: "memory");
    }

    // ---------- wait K only; scores ----------
    asm volatile("cp.async.wait_group 1;\n" ::: "memory");
    __syncthreads();
    {
        float sp[8];
        #pragma unroll
        for (int i = 0; i < 8; ++i) {
            const float4 k4 = *(const float4*)&shK[(wid*8 + i)*DIM + lane*4];
            sp[i] = q4.x*k4.x + q4.y*k4.y + q4.z*k4.z + q4.w*k4.w;
        }
        #pragma unroll
        for (int o = 16; o > 0; o >>= 1)
            #pragma unroll
            for (int i = 0; i < 8; ++i)
                sp[i] += __shfl_xor_sync(0xffffffffu, sp[i], o);
        if (lane == 0) {
            #pragma unroll
            for (int i = 0; i < 8; ++i) sh_s[wid*8 + i] = sp[i];
        }
    }
    __syncthreads();

    // ---------- single-warp softmax over 32 scores ----------
    if (wid == 0) {
        const float sc = (lane < npos) ? sh_s[lane] + sh_b[lane] : NEG_INF;
        float mx = sc;
        #pragma unroll
        for (int o = 16; o > 0; o >>= 1) mx = fmaxf(mx, __shfl_xor_sync(0xffffffffu, mx, o));
        const float pv = __expf(sc - mx);
        float sum = pv;
        #pragma unroll
        for (int o = 16; o > 0; o >>= 1) sum += __shfl_xor_sync(0xffffffffu, sum, o);
        sh_s[lane] = pv;
        if (lane == 0) { sh_red[0] = mx; sh_red[1] = sum; }
    }
    __syncthreads();
    const float M = sh_red[0];
    const float L = sh_red[1];

    // ---------- V accumulate from shared (thread reads only its own copies) ----------
    asm volatile("cp.async.wait_group 0;\n" ::: "memory");
    float acc = 0.f;
    #pragma unroll
    for (int kb = 0; kb < 2; ++kb) {
        const int li = last - (start + kb*BS);
        #pragma unroll
        for (int j4 = 0; j4 < 4; ++j4) {
            const float4 v4 = *(const float4*)&shV[(kb*512 + j4*128 + t)*4];
            float v0 = v4.x, v1 = v4.y, v2 = v4.z, v3 = v4.w;
            if (4*j4 + 0 == li) v0 = vn;
            if (4*j4 + 1 == li) v1 = vn;
            if (4*j4 + 2 == li) v2 = vn;
            if (4*j4 + 3 == li) v3 = vn;
            acc += sh_s[kb*BS + 4*j4 + 0] * v0;
            acc += sh_s[kb*BS + 4*j4 + 1] * v1;
            acc += sh_s[kb*BS + 4*j4 + 2] * v2;
            acc += sh_s[kb*BS + 4*j4 + 3] * v3;
        }
    }

    const int nch = (ctx + CHUNK - 1) / CHUNK;
    if (nch == 1) {
        out[(size_t)bh*DIM + t] = acc / L;
        return;
    }

    // ---------- partial write + fan-in merge ----------
    const int base = bh*NCHUNK;
    const int idx  = base + chunk;
    if (t == 0) { g_m[idx] = M; g_l[idx] = L; }
    g_acc[(size_t)idx*DIM + t] = acc;
    __threadfence();
    __syncthreads();
    if (t == 0) {
        const unsigned int ticket = atomicAdd(&g_cnt[bh], 1u);
        sh_red[2] = (ticket == (unsigned)(nch - 1)) ? 1.f : 0.f;
    }
    __syncthreads();
    if (sh_red[2] != 0.f) {
        float MM = NEG_INF;
        #pragma unroll 4
        for (int c = 0; c < nch; ++c) MM = fmaxf(MM, g_m[base + c]);
        float LL = 0.f, o = 0.f;
        #pragma unroll 4
        for (int c = 0; c < nch; ++c) {
            const float w = __expf(g_m[base + c] - MM);
            LL += g_l[base + c] * w;
            o  += w * g_acc[(size_t)(base + c)*DIM + t];
        }
        out[(size_t)bh*DIM + t] = o / LL;
        if (t == 0) g_cnt[bh] = 0u;
    }
}

extern "C" void kernel_launch(void* const* d_in, const int* in_sizes, int n_in,
                              void* d_out, int out_size)
{
    const float* q     = (const float*)d_in[0];
    const float* k_new = (const float*)d_in[1];
    const float* v_new = (const float*)d_in[2];
    const float* kc    = (const float*)d_in[3];
    const float* vc    = (const float*)d_in[4];
    const int*   btab  = (const int*)d_in[6];
    const int*   ctx   = (const int*)d_in[7];
    const float* bias  = (const float*)d_in[8];

    dim3 g(NCHUNK, HEADS, BATCH);
    attn_fused<<<g, 128>>>(q, k_new, v_new, kc, vc, btab, ctx, bias, (float*)d_out);
}

// round 12
// speedup vs baseline: 1.2012x; 1.2012x over previous
#include <cuda_runtime.h>
#include <math.h>

#define BATCH   16
#define HEADS   16
#define DIM     128
#define BS      16
#define MAX_CTX 1024
#define NTBL    96
#define PT_LEN  32
#define QSCALE  0.08838834764831845f
#define CHUNK   32
#define NCHUNK  32
#define NEG_INF -1e30f

__device__ float        g_m  [BATCH*HEADS*NCHUNK];
__device__ float        g_l  [BATCH*HEADS*NCHUNK];
__device__ float        g_acc[BATCH*HEADS*NCHUNK*DIM];
__device__ unsigned int g_cnt[BATCH*HEADS];          // zero-init; merger resets

__device__ __forceinline__ float4 ldg_v4(const float* p) {
    float4 v;
    asm volatile("ld.global.nc.v4.f32 {%0,%1,%2,%3}, [%4];"
                 : "=f"(v.x), "=f"(v.y), "=f"(v.z), "=f"(v.w) : "l"(p));
    return v;
}

__global__ void __launch_bounds__(128, 8) attn_fused(
    const float* __restrict__ q,
    const float* __restrict__ k_new,
    const float* __restrict__ v_new,
    const float* __restrict__ kc,
    const float* __restrict__ vc,
    const int*   __restrict__ btab,
    const int*   __restrict__ ctx_lens,
    const float* __restrict__ bias,
    float*       __restrict__ out)
{
    const int chunk = blockIdx.x;
    const int h     = blockIdx.y;
    const int b     = blockIdx.z;
    const int ctx   = ctx_lens[b];
    const int start = chunk * CHUNK;
    if (start >= ctx) return;

    const int t    = threadIdx.x;          // 0..127
    const int wid  = t >> 5;
    const int lane = t & 31;
    const int bh   = b*HEADS + h;
    const int npos = min(CHUNK, ctx - start);
    const int last = ctx - 1;

    __shared__ float shK[CHUNK*DIM];       // 16 KB K staging
    __shared__ float sh_s[CHUNK];
    __shared__ float sh_b[CHUNK];
    __shared__ int   sh_blk[CHUNK/BS];
    __shared__ float sh_red[3];

    if (t < CHUNK/BS) sh_blk[t] = btab[b*NTBL + PT_LEN + chunk*(CHUNK/BS) + t];
    if (t < CHUNK)    sh_b[t]   = bias[(size_t)bh*MAX_CTX + start + t];

    float4 q4 = ((const float4*)(q + (size_t)bh*DIM))[lane];
    q4.x *= QSCALE; q4.y *= QSCALE; q4.z *= QSCALE; q4.w *= QSCALE;
    const float vn = v_new[(size_t)bh*DIM + t];
    __syncthreads();

    // ---------- V prefetch: volatile LDGs pinned BEFORE the K wait ----------
    const float* vbase0 = vc + (((size_t)sh_blk[0]*HEADS + h)*DIM + t)*BS;
    const float* vbase1 = vc + (((size_t)sh_blk[1]*HEADS + h)*DIM + t)*BS;
    float4 va0 = ldg_v4(vbase0 +  0), va1 = ldg_v4(vbase0 +  4);
    float4 va2 = ldg_v4(vbase0 +  8), va3 = ldg_v4(vbase0 + 12);
    float4 vb0 = ldg_v4(vbase1 +  0), vb1 = ldg_v4(vbase1 +  4);
    float4 vb2 = ldg_v4(vbase1 +  8), vb3 = ldg_v4(vbase1 + 12);

    // ---------- K staging: warp `wid` streams rows wid*8..wid*8+7 via cp.async ----------
    {
        const int kb = wid >> 1;
        const int rb = (wid & 1) * 8;
        const float* kbase = kc + ((size_t)sh_blk[kb]*HEADS + h)*(BS*DIM) + rb*DIM;
        const float* knewp = k_new + (size_t)bh*DIM;
        const unsigned dbase = (unsigned)__cvta_generic_to_shared(&shK[wid*8*DIM]) + lane*16u;
        #pragma unroll
        for (int r = 0; r < 8; ++r) {
            const int pos = start + wid*8 + r;
            const float* src = ((pos == last) ? knewp : (kbase + r*DIM)) + lane*4;
            asm volatile("cp.async.cg.shared.global [%0], [%1], 16;\n"
                         :: "r"(dbase + r*(DIM*4u)), "l"(src) : "memory");
        }
        asm volatile("cp.async.commit_group;\n" ::: "memory");
        asm volatile("cp.async.wait_group 0;\n"  ::: "memory");
        __syncwarp();

        float sp[8];
        #pragma unroll
        for (int i = 0; i < 8; ++i) {
            const float4 k4 = *(const float4*)&shK[(wid*8 + i)*DIM + lane*4];
            sp[i] = q4.x*k4.x + q4.y*k4.y + q4.z*k4.z + q4.w*k4.w;
        }
        #pragma unroll
        for (int o = 16; o > 0; o >>= 1)
            #pragma unroll
            for (int i = 0; i < 8; ++i)
                sp[i] += __shfl_xor_sync(0xffffffffu, sp[i], o);
        if (lane == 0) {
            #pragma unroll
            for (int i = 0; i < 8; ++i) sh_s[wid*8 + i] = sp[i];
        }
    }
    __syncthreads();

    // ---------- single-warp softmax over 32 scores ----------
    if (wid == 0) {
        const float sc = (lane < npos) ? sh_s[lane] + sh_b[lane] : NEG_INF;
        float mx = sc;
        #pragma unroll
        for (int o = 16; o > 0; o >>= 1) mx = fmaxf(mx, __shfl_xor_sync(0xffffffffu, mx, o));
        const float pv = __expf(sc - mx);
        float sum = pv;
        #pragma unroll
        for (int o = 16; o > 0; o >>= 1) sum += __shfl_xor_sync(0xffffffffu, sum, o);
        sh_s[lane] = pv;
        if (lane == 0) { sh_red[0] = mx; sh_red[1] = sum; }
    }
    __syncthreads();
    const float M = sh_red[0];
    const float L = sh_red[1];

    // ---------- V accumulate from registers (already landed) ----------
    float acc = 0.f;
    {
        float va[16] = {va0.x,va0.y,va0.z,va0.w, va1.x,va1.y,va1.z,va1.w,
                        va2.x,va2.y,va2.z,va2.w, va3.x,va3.y,va3.z,va3.w};
        float vb[16] = {vb0.x,vb0.y,vb0.z,vb0.w, vb1.x,vb1.y,vb1.z,vb1.w,
                        vb2.x,vb2.y,vb2.z,vb2.w, vb3.x,vb3.y,vb3.z,vb3.w};
        const int li0 = last - start;
        const int li1 = last - (start + BS);
        #pragma unroll
        for (int j = 0; j < BS; ++j) {
            if (j == li0) va[j] = vn;
            if (j == li1) vb[j] = vn;
            acc += sh_s[j]      * va[j];
            acc += sh_s[BS + j] * vb[j];
        }
    }

    const int nch = (ctx + CHUNK - 1) / CHUNK;
    if (nch == 1) {
        out[(size_t)bh*DIM + t] = acc / L;
        return;
    }

    // ---------- partial write + fan-in merge ----------
    const int base = bh*NCHUNK;
    const int idx  = base + chunk;
    if (t == 0) { g_m[idx] = M; g_l[idx] = L; }
    g_acc[(size_t)idx*DIM + t] = acc;
    __threadfence();
    __syncthreads();
    if (t == 0) {
        const unsigned int ticket = atomicAdd(&g_cnt[bh], 1u);
        sh_red[2] = (ticket == (unsigned)(nch - 1)) ? 1.f : 0.f;
    }
    __syncthreads();
    if (sh_red[2] != 0.f) {
        float MM = NEG_INF;
        #pragma unroll 4
        for (int c = 0; c < nch; ++c) MM = fmaxf(MM, g_m[base + c]);
        float LL = 0.f, o = 0.f;
        #pragma unroll 4
        for (int c = 0; c < nch; ++c) {
            const float w = __expf(g_m[base + c] - MM);
            LL += g_l[base + c] * w;
            o  += w * g_acc[(size_t)(base + c)*DIM + t];
        }
        out[(size_t)bh*DIM + t] = o / LL;
        if (t == 0) g_cnt[bh] = 0u;
    }
}

extern "C" void kernel_launch(void* const* d_in, const int* in_sizes, int n_in,
                              void* d_out, int out_size)
{
    const float* q     = (const float*)d_in[0];
    const float* k_new = (const float*)d_in[1];
    const float* v_new = (const float*)d_in[2];
    const float* kc    = (const float*)d_in[3];
    const float* vc    = (const float*)d_in[4];
    const int*   btab  = (const int*)d_in[6];
    const int*   ctx   = (const int*)d_in[7];
    const float* bias  = (const float*)d_in[8];

    dim3 g(NCHUNK, HEADS, BATCH);
    attn_fused<<<g, 128>>>(q, k_new, v_new, kc, vc, btab, ctx, bias, (float*)d_out);
}